// round 2
// baseline (speedup 1.0000x reference)
#include <cuda_runtime.h>

#define NB 8
#define SS 2048
#define DD 512
#define MTOT (NB*SS)   // 16384

// ---- scratch (static device arrays; no dynamic allocation allowed) ----
__device__ float g_qp[(size_t)MTOT*DD];        // 33.5 MB
__device__ float g_kp[(size_t)MTOT*DD];        // 33.5 MB
__device__ float g_vp[(size_t)MTOT*DD];        // 33.5 MB
__device__ float g_exp[(size_t)NB*SS*SS];      // 134 MB (exp(scores))
__device__ float g_rowsum[NB*SS];

// ---- helpers ----
__device__ __forceinline__ unsigned f2tf(float x){
    unsigned r; asm("cvt.rna.tf32.f32 %0, %1;" : "=r"(r) : "f"(x)); return r;
}

__device__ __forceinline__ void mma8(float* d, const unsigned* a, const unsigned* b){
    asm volatile("mma.sync.aligned.m16n8k8.row.col.f32.tf32.tf32.f32 "
        "{%0,%1,%2,%3}, {%4,%5,%6,%7}, {%8,%9}, {%0,%1,%2,%3};"
        : "+f"(d[0]), "+f"(d[1]), "+f"(d[2]), "+f"(d[3])
        : "r"(a[0]), "r"(a[1]), "r"(a[2]), "r"(a[3]),
          "r"(b[0]), "r"(b[1]));
}

// Tile geometry: BM=128, BN=64, BK=32. 256 threads = 8 warps in 4(m) x 2(n),
// each warp computes a 32x32 tile via 2x4 m16n8k8 fragments.
// SMEM strides padded for conflict-free fragment reads:
//   A  [128][36]  (row-major, k inner)  -> bank (4r+k)%32, conflict-free
//   Bk [ 32][72]  (k-major rows, proj/PV W-style B) -> bank (8k+n)%32, conflict-free
//   Bn [ 64][36]  (n-major rows, scores kp-style B) -> bank (4n+k)%32, conflict-free

// load 128x32 fp32 tile -> smem tf32, stride 36
__device__ __forceinline__ void load_tile_128x32(unsigned* As, const float* A, int lda){
    int tid = threadIdx.x;
    #pragma unroll
    for (int i = 0; i < 4; i++){
        int id = tid + i*256;             // 1024 float4 total
        int r = id >> 3, c4 = (id & 7) << 2;
        float4 v = *(const float4*)(A + (size_t)r*lda + c4);
        uint4 u = { f2tf(v.x), f2tf(v.y), f2tf(v.z), f2tf(v.w) };
        *(uint4*)(As + r*36 + c4) = u;
    }
}
// load 32x64 tile -> stride 72 (k-major B)
__device__ __forceinline__ void load_tile_32x64(unsigned* Bs, const float* Bg, int ldb){
    int tid = threadIdx.x;
    #pragma unroll
    for (int i = 0; i < 2; i++){
        int id = tid + i*256;             // 512 float4 total
        int r = id >> 4, c4 = (id & 15) << 2;
        float4 v = *(const float4*)(Bg + (size_t)r*ldb + c4);
        uint4 u = { f2tf(v.x), f2tf(v.y), f2tf(v.z), f2tf(v.w) };
        *(uint4*)(Bs + r*72 + c4) = u;
    }
}
// load 64x32 tile -> stride 36 (n-major B, scores)
__device__ __forceinline__ void load_tile_64x32(unsigned* Bs, const float* Bg, int ldb){
    int tid = threadIdx.x;
    #pragma unroll
    for (int i = 0; i < 2; i++){
        int id = tid + i*256;             // 512 float4 total
        int r = id >> 3, c4 = (id & 7) << 2;
        float4 v = *(const float4*)(Bg + (size_t)r*ldb + c4);
        uint4 u = { f2tf(v.x), f2tf(v.y), f2tf(v.z), f2tf(v.w) };
        *(uint4*)(Bs + r*36 + c4) = u;
    }
}

// one BK=32 tile of MMAs. NMAJOR=0: B in Bs[k][n] stride 72; NMAJOR=1: Bs[n][k] stride 36
template<int NMAJOR>
__device__ __forceinline__ void mma_tile(float acc[2][4][4], const unsigned* As, const unsigned* Bs){
    int lane = threadIdx.x & 31;
    int warp = threadIdx.x >> 5;
    int wm = warp & 3, wn = warp >> 2;
    int g = lane >> 2, tg = lane & 3;
    #pragma unroll
    for (int kk = 0; kk < 4; kk++){
        int k0 = kk*8 + tg;
        unsigned a[2][4];
        #pragma unroll
        for (int mi = 0; mi < 2; mi++){
            int r = wm*32 + mi*16 + g;
            a[mi][0] = As[r*36 + k0];
            a[mi][1] = As[(r+8)*36 + k0];
            a[mi][2] = As[r*36 + k0 + 4];
            a[mi][3] = As[(r+8)*36 + k0 + 4];
        }
        #pragma unroll
        for (int ni = 0; ni < 4; ni++){
            int n = wn*32 + ni*8 + g;
            unsigned b[2];
            if (NMAJOR){ b[0] = Bs[n*36 + k0];  b[1] = Bs[n*36 + k0 + 4]; }
            else       { b[0] = Bs[k0*72 + n];  b[1] = Bs[(k0+4)*72 + n]; }
            #pragma unroll
            for (int mi = 0; mi < 2; mi++)
                mma8(acc[mi][ni], a[mi], b);
        }
    }
}

// ============ kernel 1: projections (qp/kp/vp), grid.z selects which ============
__global__ __launch_bounds__(256) void proj_kernel(
    const float* q, const float* kin, const float* vin,
    const float* Wq, const float* bq,
    const float* Wk, const float* bk,
    const float* Wv, const float* bv)
{
    __shared__ unsigned As[128*36];
    __shared__ unsigned Bs[32*72];
    const float *A, *W, *bias; float* C;
    if      (blockIdx.z == 0){ A = q;   W = Wq; bias = bq; C = g_qp; }
    else if (blockIdx.z == 1){ A = kin; W = Wk; bias = bk; C = g_kp; }
    else                     { A = vin; W = Wv; bias = bv; C = g_vp; }

    int m0 = blockIdx.y * 128, n0 = blockIdx.x * 64;
    float acc[2][4][4] = {};

    for (int kt = 0; kt < DD; kt += 32){
        load_tile_128x32(As, A + (size_t)m0*DD + kt, DD);
        load_tile_32x64 (Bs, W + (size_t)kt*DD + n0, DD);
        __syncthreads();
        mma_tile<0>(acc, As, Bs);
        __syncthreads();
    }

    int lane = threadIdx.x & 31, warp = threadIdx.x >> 5;
    int wm = warp & 3, wn = warp >> 2;
    int g = lane >> 2, tg = lane & 3;
    #pragma unroll
    for (int mi = 0; mi < 2; mi++){
        int r0 = m0 + wm*32 + mi*16 + g;
        #pragma unroll
        for (int ni = 0; ni < 4; ni++){
            int c0 = n0 + wn*32 + ni*8 + 2*tg;
            float b0 = bias[c0], b1 = bias[c0+1];
            float2 v0 = make_float2(acc[mi][ni][0] + b0, acc[mi][ni][1] + b1);
            float2 v1 = make_float2(acc[mi][ni][2] + b0, acc[mi][ni][3] + b1);
            *(float2*)(C + (size_t)r0*DD + c0)     = v0;
            *(float2*)(C + (size_t)(r0+8)*DD + c0) = v1;
        }
    }
}

// ============ kernel 2: E = exp(qp @ kp^T * scale), per-batch ============
__global__ __launch_bounds__(256) void scores_kernel()
{
    __shared__ unsigned As[128*36];
    __shared__ unsigned Bs[64*36];
    int b = blockIdx.z;
    const float* A  = g_qp + (size_t)b*SS*DD;
    const float* Bg = g_kp + (size_t)b*SS*DD;
    float* C = g_exp + (size_t)b*SS*SS;

    int m0 = blockIdx.y * 128, n0 = blockIdx.x * 64;
    float acc[2][4][4] = {};

    for (int kt = 0; kt < DD; kt += 32){
        load_tile_128x32(As, A  + (size_t)m0*DD + kt, DD);
        load_tile_64x32 (Bs, Bg + (size_t)n0*DD + kt, DD);
        __syncthreads();
        mma_tile<1>(acc, As, Bs);
        __syncthreads();
    }

    const float scale = 0.04419417382415922f;  // 1/sqrt(512)
    int lane = threadIdx.x & 31, warp = threadIdx.x >> 5;
    int wm = warp & 3, wn = warp >> 2;
    int g = lane >> 2, tg = lane & 3;
    #pragma unroll
    for (int mi = 0; mi < 2; mi++){
        int r0 = m0 + wm*32 + mi*16 + g;
        #pragma unroll
        for (int ni = 0; ni < 4; ni++){
            int c0 = n0 + wn*32 + ni*8 + 2*tg;
            float2 v0 = make_float2(__expf(acc[mi][ni][0]*scale), __expf(acc[mi][ni][1]*scale));
            float2 v1 = make_float2(__expf(acc[mi][ni][2]*scale), __expf(acc[mi][ni][3]*scale));
            *(float2*)(C + (size_t)r0*SS + c0)     = v0;
            *(float2*)(C + (size_t)(r0+8)*SS + c0) = v1;
        }
    }
}

// ============ kernel 3: rowsum of E ============
__global__ __launch_bounds__(256) void rowsum_kernel()
{
    __shared__ float red[8];
    int row = blockIdx.x;                      // 0..16383 == b*2048 + q
    const float4* E = (const float4*)(g_exp + (size_t)row*SS);
    float s = 0.f;
    #pragma unroll
    for (int i = 0; i < 2; i++){
        float4 v = E[threadIdx.x + i*256];
        s += (v.x + v.y) + (v.z + v.w);
    }
    #pragma unroll
    for (int o = 16; o; o >>= 1) s += __shfl_xor_sync(0xffffffffu, s, o);
    if ((threadIdx.x & 31) == 0) red[threadIdx.x >> 5] = s;
    __syncthreads();
    if (threadIdx.x < 8){
        s = red[threadIdx.x];
        #pragma unroll
        for (int o = 4; o; o >>= 1) s += __shfl_xor_sync(0xffu, s, o);
        if (threadIdx.x == 0) g_rowsum[row] = s;
    }
}

// ============ kernel 4: out = (E @ vp) / rowsum, per-batch ============
__global__ __launch_bounds__(256) void pv_kernel(float* out)
{
    __shared__ unsigned As[128*36];
    __shared__ unsigned Bs[32*72];
    int b = blockIdx.z;
    const float* A  = g_exp + (size_t)b*SS*SS;
    const float* Bg = g_vp  + (size_t)b*SS*DD;
    float* C = out + (size_t)b*SS*DD;

    int m0 = blockIdx.y * 128, n0 = blockIdx.x * 64;
    float acc[2][4][4] = {};

    for (int kt = 0; kt < SS; kt += 32){
        load_tile_128x32(As, A  + (size_t)m0*SS + kt, SS);
        load_tile_32x64 (Bs, Bg + (size_t)kt*DD + n0, DD);
        __syncthreads();
        mma_tile<0>(acc, As, Bs);
        __syncthreads();
    }

    int lane = threadIdx.x & 31, warp = threadIdx.x >> 5;
    int wm = warp & 3, wn = warp >> 2;
    int g = lane >> 2, tg = lane & 3;
    #pragma unroll
    for (int mi = 0; mi < 2; mi++){
        int r0 = m0 + wm*32 + mi*16 + g;
        float inv0 = 1.0f / g_rowsum[(size_t)b*SS + r0];
        float inv1 = 1.0f / g_rowsum[(size_t)b*SS + r0 + 8];
        #pragma unroll
        for (int ni = 0; ni < 4; ni++){
            int c0 = n0 + wn*32 + ni*8 + 2*tg;
            float2 v0 = make_float2(acc[mi][ni][0]*inv0, acc[mi][ni][1]*inv0);
            float2 v1 = make_float2(acc[mi][ni][2]*inv1, acc[mi][ni][3]*inv1);
            *(float2*)(C + (size_t)r0*DD + c0)     = v0;
            *(float2*)(C + (size_t)(r0+8)*DD + c0) = v1;
        }
    }
}

// ============ launch ============
extern "C" void kernel_launch(void* const* d_in, const int* in_sizes, int n_in,
                              void* d_out, int out_size)
{
    const float* q  = (const float*)d_in[0];
    const float* k  = (const float*)d_in[1];
    const float* v  = (const float*)d_in[2];
    const float* Wq = (const float*)d_in[3];
    const float* bq = (const float*)d_in[4];
    const float* Wk = (const float*)d_in[5];
    const float* bk = (const float*)d_in[6];
    const float* Wv = (const float*)d_in[7];
    const float* bv = (const float*)d_in[8];
    float* out = (float*)d_out;

    // 1) projections: C[16384,512] = X @ W + b, z = {q,k,v}
    proj_kernel<<<dim3(DD/64, MTOT/128, 3), 256>>>(q, k, v, Wq, bq, Wk, bk, Wv, bv);
    // 2) E = exp(scaled scores), per batch [2048,2048]
    scores_kernel<<<dim3(SS/64, SS/128, NB), 256>>>();
    // 3) row sums of E
    rowsum_kernel<<<MTOT, 256>>>();
    // 4) out = (E @ vp) / rowsum
    pv_kernel<<<dim3(DD/64, SS/128, NB), 256>>>(out);
}

// round 3
// speedup vs baseline: 1.2944x; 1.2944x over previous
#include <cuda_runtime.h>

#define NB 8
#define SS 2048
#define DD 512
#define MTOT (NB*SS)   // 16384

// Block tile: BM=128, BN=256, BK=32. 256 threads = 8 warps (wm in {0,1}, wn in {0..3}),
// each warp computes a 64x64 tile via 4x8 m16n8k8 tf32 fragments.
// SMEM (fp32 raw bits, truncation-tf32), padded strides:
//   A  [128][36]   row-major (k inner)      -> conflict-free
//   Bk [ 32][264]  k-major rows (W / vp)    -> conflict-free (264 % 32 == 8)
//   Bn [256][36]   n-major rows (kp scores) -> conflict-free

#define A_STAGE  (128*36)
#define BK_STAGE (32*264)
#define BN_STAGE (256*36)

// ---- scratch ----
__device__ float g_qp[(size_t)MTOT*DD];
__device__ float g_kp[(size_t)MTOT*DD];
__device__ float g_vp[(size_t)MTOT*DD];
__device__ float g_exp[(size_t)NB*SS*SS];
__device__ float g_rowsum[MTOT];

// ---- helpers ----
__device__ __forceinline__ unsigned sptr(const void* p){
    return (unsigned)__cvta_generic_to_shared(p);
}
__device__ __forceinline__ void cp16(unsigned s, const void* g){
    asm volatile("cp.async.cg.shared.global [%0], [%1], 16;" :: "r"(s), "l"(g));
}
__device__ __forceinline__ void cp_commit(){ asm volatile("cp.async.commit_group;"); }
__device__ __forceinline__ void cp_wait1(){ asm volatile("cp.async.wait_group 1;"); }
__device__ __forceinline__ void cp_wait0(){ asm volatile("cp.async.wait_group 0;"); }

__device__ __forceinline__ void mma8(float* d, const unsigned* a, const unsigned* b){
    asm volatile("mma.sync.aligned.m16n8k8.row.col.f32.tf32.tf32.f32 "
        "{%0,%1,%2,%3}, {%4,%5,%6,%7}, {%8,%9}, {%0,%1,%2,%3};"
        : "+f"(d[0]), "+f"(d[1]), "+f"(d[2]), "+f"(d[3])
        : "r"(a[0]), "r"(a[1]), "r"(a[2]), "r"(a[3]),
          "r"(b[0]), "r"(b[1]));
}

// ---- async tile loaders (256 threads) ----
__device__ __forceinline__ void load_A(unsigned* As, const float* A, int lda){
    int tid = threadIdx.x;
    #pragma unroll
    for (int i = 0; i < 4; i++){               // 1024 x 16B
        int id = tid + i*256;
        int r = id >> 3, c4 = (id & 7) << 2;
        cp16(sptr(As + r*36 + c4), A + (size_t)r*lda + c4);
    }
}
__device__ __forceinline__ void load_Bk(unsigned* Bs, const float* B, int ldb){  // 32x256
    int tid = threadIdx.x;
    #pragma unroll
    for (int i = 0; i < 8; i++){               // 2048 x 16B
        int id = tid + i*256;
        int r = id >> 6, c4 = (id & 63) << 2;
        cp16(sptr(Bs + r*264 + c4), B + (size_t)r*ldb + c4);
    }
}
__device__ __forceinline__ void load_Bn(unsigned* Bs, const float* B, int ldb){  // 256x32
    int tid = threadIdx.x;
    #pragma unroll
    for (int i = 0; i < 8; i++){               // 2048 x 16B
        int id = tid + i*256;
        int r = id >> 3, c4 = (id & 7) << 2;
        cp16(sptr(Bs + r*36 + c4), B + (size_t)r*ldb + c4);
    }
}

// one BK=32 tile of MMAs for a 64x64 warp tile.
// NMAJOR=0: Bs[k][n] stride 264; NMAJOR=1: Bs[n][k] stride 36
template<int NMAJOR>
__device__ __forceinline__ void mma_tile8(float acc[4][8][4], const unsigned* As, const unsigned* Bs){
    int lane = threadIdx.x & 31, warp = threadIdx.x >> 5;
    int wm = warp & 1, wn = warp >> 1;
    int g = lane >> 2, tg = lane & 3;
    #pragma unroll
    for (int kk = 0; kk < 4; kk++){
        int k0 = kk*8 + tg;
        unsigned a[4][4];
        #pragma unroll
        for (int mi = 0; mi < 4; mi++){
            int r = wm*64 + mi*16 + g;
            a[mi][0] = As[r*36 + k0];
            a[mi][1] = As[(r+8)*36 + k0];
            a[mi][2] = As[r*36 + k0 + 4];
            a[mi][3] = As[(r+8)*36 + k0 + 4];
        }
        #pragma unroll
        for (int ni = 0; ni < 8; ni++){
            int n = wn*64 + ni*8 + g;
            unsigned b[2];
            if (NMAJOR){ b[0] = Bs[n*36 + k0];   b[1] = Bs[n*36 + k0 + 4]; }
            else       { b[0] = Bs[k0*264 + n];  b[1] = Bs[(k0+4)*264 + n]; }
            #pragma unroll
            for (int mi = 0; mi < 4; mi++)
                mma8(acc[mi][ni], a[mi], b);
        }
    }
}

// ============ kernel 1: projections ============
__global__ __launch_bounds__(256, 1) void proj_kernel(
    const float* q, const float* kin, const float* vin,
    const float* Wq, const float* bq,
    const float* Wk, const float* bk,
    const float* Wv, const float* bv)
{
    extern __shared__ unsigned sh[];
    unsigned* As = sh;
    unsigned* Bs = sh + 2*A_STAGE;

    const float *A, *W, *bias; float* C;
    if      (blockIdx.z == 0){ A = q;   W = Wq; bias = bq; C = g_qp; }
    else if (blockIdx.z == 1){ A = kin; W = Wk; bias = bk; C = g_kp; }
    else                     { A = vin; W = Wv; bias = bv; C = g_vp; }

    int m0 = blockIdx.y * 128, n0 = blockIdx.x * 256;
    float acc[4][8][4] = {};

    const float* Ab = A + (size_t)m0*DD;
    const float* Wb = W + n0;

    load_A(As, Ab, DD);
    load_Bk(Bs, Wb, DD);
    cp_commit();
    const int nIter = DD/32;
    for (int it = 0; it < nIter; it++){
        if (it + 1 < nIter){
            load_A (As + ((it+1)&1)*A_STAGE,  Ab + (it+1)*32,            DD);
            load_Bk(Bs + ((it+1)&1)*BK_STAGE, Wb + (size_t)(it+1)*32*DD, DD);
            cp_commit(); cp_wait1();
        } else cp_wait0();
        __syncthreads();
        mma_tile8<0>(acc, As + (it&1)*A_STAGE, Bs + (it&1)*BK_STAGE);
        __syncthreads();
    }

    int lane = threadIdx.x & 31, warp = threadIdx.x >> 5;
    int wm = warp & 1, wn = warp >> 1;
    int g = lane >> 2, tg = lane & 3;
    #pragma unroll
    for (int mi = 0; mi < 4; mi++){
        int r0 = m0 + wm*64 + mi*16 + g;
        #pragma unroll
        for (int ni = 0; ni < 8; ni++){
            int c0 = n0 + wn*64 + ni*8 + 2*tg;
            float b0 = bias[c0], b1 = bias[c0+1];
            float2 v0 = make_float2(acc[mi][ni][0] + b0, acc[mi][ni][1] + b1);
            float2 v1 = make_float2(acc[mi][ni][2] + b0, acc[mi][ni][3] + b1);
            *(float2*)(C + (size_t)r0*DD + c0)     = v0;
            *(float2*)(C + (size_t)(r0+8)*DD + c0) = v1;
        }
    }
}

// ============ kernel 2: E = exp(qp @ kp^T * scale) ============
__global__ __launch_bounds__(256, 1) void scores_kernel()
{
    extern __shared__ unsigned sh[];
    unsigned* As = sh;
    unsigned* Bs = sh + 2*A_STAGE;

    int b = blockIdx.z;
    const float* A  = g_qp + (size_t)b*SS*DD;
    const float* Bg = g_kp + (size_t)b*SS*DD;
    float* C = g_exp + (size_t)b*SS*SS;

    int m0 = blockIdx.y * 128, n0 = blockIdx.x * 256;
    float acc[4][8][4] = {};

    const float* Ab = A  + (size_t)m0*DD;
    const float* Bb = Bg + (size_t)n0*DD;

    load_A(As, Ab, DD);
    load_Bn(Bs, Bb, DD);
    cp_commit();
    const int nIter = DD/32;
    for (int it = 0; it < nIter; it++){
        if (it + 1 < nIter){
            load_A (As + ((it+1)&1)*A_STAGE,  Ab + (it+1)*32, DD);
            load_Bn(Bs + ((it+1)&1)*BN_STAGE, Bb + (it+1)*32, DD);
            cp_commit(); cp_wait1();
        } else cp_wait0();
        __syncthreads();
        mma_tile8<1>(acc, As + (it&1)*A_STAGE, Bs + (it&1)*BN_STAGE);
        __syncthreads();
    }

    const float scale = 0.04419417382415922f;  // 1/sqrt(512)
    int lane = threadIdx.x & 31, warp = threadIdx.x >> 5;
    int wm = warp & 1, wn = warp >> 1;
    int g = lane >> 2, tg = lane & 3;
    #pragma unroll
    for (int mi = 0; mi < 4; mi++){
        int r0 = m0 + wm*64 + mi*16 + g;
        #pragma unroll
        for (int ni = 0; ni < 8; ni++){
            int c0 = n0 + wn*64 + ni*8 + 2*tg;
            float2 v0 = make_float2(__expf(acc[mi][ni][0]*scale), __expf(acc[mi][ni][1]*scale));
            float2 v1 = make_float2(__expf(acc[mi][ni][2]*scale), __expf(acc[mi][ni][3]*scale));
            *(float2*)(C + (size_t)r0*SS + c0)     = v0;
            *(float2*)(C + (size_t)(r0+8)*SS + c0) = v1;
        }
    }
}

// ============ kernel 3: rowsum of E ============
__global__ __launch_bounds__(256) void rowsum_kernel()
{
    __shared__ float red[8];
    int row = blockIdx.x;
    const float4* E = (const float4*)(g_exp + (size_t)row*SS);
    float s = 0.f;
    #pragma unroll
    for (int i = 0; i < 2; i++){
        float4 v = E[threadIdx.x + i*256];
        s += (v.x + v.y) + (v.z + v.w);
    }
    #pragma unroll
    for (int o = 16; o; o >>= 1) s += __shfl_xor_sync(0xffffffffu, s, o);
    if ((threadIdx.x & 31) == 0) red[threadIdx.x >> 5] = s;
    __syncthreads();
    if (threadIdx.x < 8){
        s = red[threadIdx.x];
        #pragma unroll
        for (int o = 4; o; o >>= 1) s += __shfl_xor_sync(0xffu, s, o);
        if (threadIdx.x == 0) g_rowsum[row] = s;
    }
}

// ============ kernel 4: out = (E @ vp) / rowsum ============
__global__ __launch_bounds__(256, 1) void pv_kernel(float* out)
{
    extern __shared__ unsigned sh[];
    unsigned* As = sh;
    unsigned* Bs = sh + 2*A_STAGE;

    int b = blockIdx.z;
    const float* A  = g_exp + (size_t)b*SS*SS;
    const float* Bg = g_vp  + (size_t)b*SS*DD;
    float* C = out + (size_t)b*SS*DD;

    int m0 = blockIdx.y * 128, n0 = blockIdx.x * 256;
    float acc[4][8][4] = {};

    const float* Ab = A  + (size_t)m0*SS;
    const float* Bb = Bg + n0;

    load_A(As, Ab, SS);
    load_Bk(Bs, Bb, DD);
    cp_commit();
    const int nIter = SS/32;
    for (int it = 0; it < nIter; it++){
        if (it + 1 < nIter){
            load_A (As + ((it+1)&1)*A_STAGE,  Ab + (it+1)*32,            SS);
            load_Bk(Bs + ((it+1)&1)*BK_STAGE, Bb + (size_t)(it+1)*32*DD, DD);
            cp_commit(); cp_wait1();
        } else cp_wait0();
        __syncthreads();
        mma_tile8<0>(acc, As + (it&1)*A_STAGE, Bs + (it&1)*BK_STAGE);
        __syncthreads();
    }

    int lane = threadIdx.x & 31, warp = threadIdx.x >> 5;
    int wm = warp & 1, wn = warp >> 1;
    int g = lane >> 2, tg = lane & 3;
    #pragma unroll
    for (int mi = 0; mi < 4; mi++){
        int r0 = m0 + wm*64 + mi*16 + g;
        float inv0 = 1.0f / g_rowsum[(size_t)b*SS + r0];
        float inv1 = 1.0f / g_rowsum[(size_t)b*SS + r0 + 8];
        #pragma unroll
        for (int ni = 0; ni < 8; ni++){
            int c0 = n0 + wn*64 + ni*8 + 2*tg;
            float2 v0 = make_float2(acc[mi][ni][0]*inv0, acc[mi][ni][1]*inv0);
            float2 v1 = make_float2(acc[mi][ni][2]*inv1, acc[mi][ni][3]*inv1);
            *(float2*)(C + (size_t)r0*DD + c0)     = v0;
            *(float2*)(C + (size_t)(r0+8)*DD + c0) = v1;
        }
    }
}

// ============ launch ============
extern "C" void kernel_launch(void* const* d_in, const int* in_sizes, int n_in,
                              void* d_out, int out_size)
{
    const float* q  = (const float*)d_in[0];
    const float* k  = (const float*)d_in[1];
    const float* v  = (const float*)d_in[2];
    const float* Wq = (const float*)d_in[3];
    const float* bq = (const float*)d_in[4];
    const float* Wk = (const float*)d_in[5];
    const float* bk = (const float*)d_in[6];
    const float* Wv = (const float*)d_in[7];
    const float* bv = (const float*)d_in[8];
    float* out = (float*)d_out;

    const int smem_k = (2*A_STAGE + 2*BK_STAGE) * 4;   // 104448 B
    const int smem_n = (2*A_STAGE + 2*BN_STAGE) * 4;   // 110592 B
    cudaFuncSetAttribute(proj_kernel,   cudaFuncAttributeMaxDynamicSharedMemorySize, smem_k);
    cudaFuncSetAttribute(scores_kernel, cudaFuncAttributeMaxDynamicSharedMemorySize, smem_n);
    cudaFuncSetAttribute(pv_kernel,     cudaFuncAttributeMaxDynamicSharedMemorySize, smem_k);

    proj_kernel<<<dim3(DD/256, MTOT/128, 3), 256, smem_k>>>(q, k, v, Wq, bq, Wk, bk, Wv, bv);
    scores_kernel<<<dim3(SS/256, SS/128, NB), 256, smem_n>>>();
    rowsum_kernel<<<MTOT, 256>>>();
    pv_kernel<<<dim3(DD/256, SS/128, NB), 256, smem_k>>>(out);
}

// round 5
// speedup vs baseline: 2.1898x; 1.6918x over previous
#include <cuda_runtime.h>
#include <cuda_fp16.h>
#include <cstdint>

#define NB 8
#define SS 2048
#define DD 512
#define MTOT (NB*SS)   // 16384

// GEMM tile: BM=128, BN=256, BK=64 halfs. 8 warps (wm in {0,1}, wn in {0..3}),
// warp tile 64x64 via 4x8 m16n8k16 fp16 fragments (fp32 accum).
// SMEM: uint32 words (= fp16 pairs along k). Row = 32 words + 4 pad = 36.
// Fragment LDS banks: (4*g + tg) % 32 -> conflict-free.
#define BKH 64
#define PAD 36
#define A_WORDS (BM_*PAD)
#define BM_ 128
#define BN_ 256
#define AW (128*PAD)              // 4608 words
#define BW (256*PAD)              // 9216 words
#define STG_W (AW + BW)           // 13824 words = 55296 B
#define NSTAGE 3
#define SMEM_BYTES (NSTAGE*STG_W*4)   // 165888

// ---- scratch (static; no dynamic allocation) ----
__device__ __align__(128) __half g_qh [(size_t)MTOT*DD];
__device__ __align__(128) __half g_kh [(size_t)MTOT*DD];
__device__ __align__(128) __half g_vh [(size_t)MTOT*DD];
__device__ __align__(128) __half g_wt [(size_t)3*DD*DD];    // [z][n][k]
__device__ __align__(128) __half g_qph[(size_t)MTOT*DD];
__device__ __align__(128) __half g_kph[(size_t)MTOT*DD];
__device__ __align__(128) __half g_vpt[(size_t)MTOT*DD];    // [b][d][s]
__device__ __align__(128) __half g_exph[(size_t)NB*SS*SS];  // 67 MB
__device__ float g_rowsum[MTOT];

// ---- ptx helpers ----
__device__ __forceinline__ unsigned sptr(const void* p){
    return (unsigned)__cvta_generic_to_shared(p);
}
__device__ __forceinline__ void cp16(unsigned s, const void* g){
    asm volatile("cp.async.cg.shared.global [%0], [%1], 16;" :: "r"(s), "l"(g));
}
__device__ __forceinline__ void cp_commit(){ asm volatile("cp.async.commit_group;"); }
__device__ __forceinline__ void cp_wait2(){ asm volatile("cp.async.wait_group 2;"); }
__device__ __forceinline__ void cp_wait1(){ asm volatile("cp.async.wait_group 1;"); }
__device__ __forceinline__ void cp_wait0(){ asm volatile("cp.async.wait_group 0;"); }

__device__ __forceinline__ void mma16(float* d, const unsigned* a, const unsigned* b){
    asm volatile("mma.sync.aligned.m16n8k16.row.col.f32.f16.f16.f32 "
        "{%0,%1,%2,%3}, {%4,%5,%6,%7}, {%8,%9}, {%0,%1,%2,%3};"
        : "+f"(d[0]), "+f"(d[1]), "+f"(d[2]), "+f"(d[3])
        : "r"(a[0]), "r"(a[1]), "r"(a[2]), "r"(a[3]),
          "r"(b[0]), "r"(b[1]));
}

// ---- async tile loaders (256 threads). lda/ldb in halfs. ----
__device__ __forceinline__ void load_A(unsigned* As, const __half* A, int lda){
    int tid = threadIdx.x;
    #pragma unroll
    for (int i = 0; i < 4; i++){              // 128 rows x 8 chunks(16B) = 1024
        int id = tid + i*256;
        int r = id >> 3, ch = id & 7;
        cp16(sptr(As + r*PAD + ch*4), A + (size_t)r*lda + ch*8);
    }
}
__device__ __forceinline__ void load_B(unsigned* Bs, const __half* B, int ldb){
    int tid = threadIdx.x;
    #pragma unroll
    for (int i = 0; i < 8; i++){              // 256 rows x 8 chunks = 2048
        int id = tid + i*256;
        int r = id >> 3, ch = id & 7;
        cp16(sptr(Bs + r*PAD + ch*4), B + (size_t)r*ldb + ch*8);
    }
}

// one BK=64 tile of MMAs for a 64x64 warp tile
__device__ __forceinline__ void mma_tile(float acc[4][8][4], const unsigned* As, const unsigned* Bs){
    int lane = threadIdx.x & 31, warp = threadIdx.x >> 5;
    int wm = warp & 1, wn = warp >> 1;
    int g = lane >> 2, tg = lane & 3;
    #pragma unroll
    for (int ks = 0; ks < 4; ks++){           // 4 k-steps of 16
        int w0 = ks*8 + tg;
        unsigned a[4][4];
        #pragma unroll
        for (int mi = 0; mi < 4; mi++){
            int r = wm*64 + mi*16 + g;
            a[mi][0] = As[r*PAD + w0];
            a[mi][1] = As[(r+8)*PAD + w0];
            a[mi][2] = As[r*PAD + w0 + 4];
            a[mi][3] = As[(r+8)*PAD + w0 + 4];
        }
        #pragma unroll
        for (int ni = 0; ni < 8; ni++){
            int n = wn*64 + ni*8 + g;
            unsigned b[2];
            b[0] = Bs[n*PAD + w0];
            b[1] = Bs[n*PAD + w0 + 4];
            #pragma unroll
            for (int mi = 0; mi < 4; mi++)
                mma16(acc[mi][ni], a[mi], b);
        }
    }
}

// C[128,256] = A[128,K] @ B[256,K]^T, 3-stage cp.async ring
__device__ __forceinline__ void gemm_main(unsigned* sh,
    const __half* A, int lda, const __half* B, int ldb, int nk, float acc[4][8][4])
{
    load_A(sh, A, lda);
    load_B(sh + AW, B, ldb);
    cp_commit();
    load_A(sh + STG_W, A + BKH, lda);
    load_B(sh + STG_W + AW, B + BKH, ldb);
    cp_commit();

    int s = 0;
    for (int it = 0; it < nk; it++){
        int nx = it + 2;
        if (nx < nk){
            int sn = s + 2; if (sn >= NSTAGE) sn -= NSTAGE;
            load_A(sh + sn*STG_W,      A + (size_t)nx*BKH, lda);
            load_B(sh + sn*STG_W + AW, B + (size_t)nx*BKH, ldb);
            cp_commit();
            cp_wait2();
        } else {
            if (nk - 1 - it == 1) cp_wait1(); else cp_wait0();
        }
        __syncthreads();
        mma_tile(acc, sh + s*STG_W, sh + s*STG_W + AW);
        __syncthreads();
        s++; if (s == NSTAGE) s = 0;
    }
}

// ================= prep kernels =================
__global__ void cvt_half(const float4* q, const float4* k, const float4* v){
    const float4* src = (blockIdx.z == 0) ? q : (blockIdx.z == 1) ? k : v;
    __half* dst = (blockIdx.z == 0) ? g_qh : (blockIdx.z == 1) ? g_kh : g_vh;
    size_t i = (size_t)blockIdx.x*blockDim.x + threadIdx.x;   // 1048576 threads, 8 elems each
    float4 a = src[2*i], b = src[2*i+1];
    __half2 h[4];
    h[0] = __floats2half2_rn(a.x, a.y);
    h[1] = __floats2half2_rn(a.z, a.w);
    h[2] = __floats2half2_rn(b.x, b.y);
    h[3] = __floats2half2_rn(b.z, b.w);
    *(uint4*)(dst + 8*i) = *(uint4*)h;
}

__global__ void wt_t(const float* Wq, const float* Wk, const float* Wv){
    __shared__ float t[32][33];
    const float* W = (blockIdx.z == 0) ? Wq : (blockIdx.z == 1) ? Wk : Wv;
    int bn = blockIdx.x*32, bk = blockIdx.y*32;
    int tx = threadIdx.x, ty = threadIdx.y;                   // 32 x 8
    #pragma unroll
    for (int j = 0; j < 4; j++)
        t[ty + 8*j][tx] = W[(size_t)(bk + ty + 8*j)*DD + bn + tx];
    __syncthreads();
    __half* O = g_wt + (size_t)blockIdx.z*DD*DD;
    #pragma unroll
    for (int j = 0; j < 4; j++)
        O[(size_t)(bn + ty + 8*j)*DD + bk + tx] = __float2half_rn(t[tx][ty + 8*j]);
}

// ================= GEMM kernels =================
__global__ __launch_bounds__(256, 1) void proj_tc(const float* bq, const float* bk, const float* bv){
    extern __shared__ unsigned sh[];
    int z = blockIdx.z;
    const __half* A = (z == 0) ? g_qh : (z == 1) ? g_kh : g_vh;
    const __half* B = g_wt + (size_t)z*DD*DD;
    const float* bias = (z == 0) ? bq : (z == 1) ? bk : bv;
    int m0 = blockIdx.y*128, n0 = blockIdx.x*256;
    float acc[4][8][4] = {};
    gemm_main(sh, A + (size_t)m0*DD, DD, B + (size_t)n0*DD, DD, DD/BKH, acc);

    int lane = threadIdx.x & 31, warp = threadIdx.x >> 5;
    int wm = warp & 1, wn = warp >> 1;
    int g = lane >> 2, tg = lane & 3;
    if (z < 2){
        __half* C = (z == 0) ? g_qph : g_kph;
        #pragma unroll
        for (int mi = 0; mi < 4; mi++){
            int r = m0 + wm*64 + mi*16 + g;
            #pragma unroll
            for (int ni = 0; ni < 8; ni++){
                int c = n0 + wn*64 + ni*8 + 2*tg;
                float2 bb = *(const float2*)(bias + c);
                *(__half2*)(C + (size_t)r*DD + c) =
                    __floats2half2_rn(acc[mi][ni][0] + bb.x, acc[mi][ni][1] + bb.y);
                *(__half2*)(C + (size_t)(r+8)*DD + c) =
                    __floats2half2_rn(acc[mi][ni][2] + bb.x, acc[mi][ni][3] + bb.y);
            }
        }
    } else {
        int b = m0 >> 11, s0 = m0 & (SS-1);
        #pragma unroll
        for (int mi = 0; mi < 4; mi++){
            int s = s0 + wm*64 + mi*16 + g;
            #pragma unroll
            for (int ni = 0; ni < 8; ni++){
                int c = n0 + wn*64 + ni*8 + 2*tg;
                float2 bb = *(const float2*)(bias + c);
                __half* base0 = g_vpt + (size_t)(b*DD + c)*SS;
                __half* base1 = g_vpt + (size_t)(b*DD + c + 1)*SS;
                base0[s]   = __float2half_rn(acc[mi][ni][0] + bb.x);
                base1[s]   = __float2half_rn(acc[mi][ni][1] + bb.y);
                base0[s+8] = __float2half_rn(acc[mi][ni][2] + bb.x);
                base1[s+8] = __float2half_rn(acc[mi][ni][3] + bb.y);
            }
        }
    }
}

__global__ __launch_bounds__(256, 1) void scores_tc(){
    extern __shared__ unsigned sh[];
    int b = blockIdx.z;
    int m0 = blockIdx.y*128, n0 = blockIdx.x*256;
    float acc[4][8][4] = {};
    gemm_main(sh, g_qph + (size_t)(b*SS + m0)*DD, DD,
                  g_kph + (size_t)(b*SS + n0)*DD, DD, DD/BKH, acc);

    const float scale = 0.04419417382415922f;   // 1/sqrt(512)
    int lane = threadIdx.x & 31, warp = threadIdx.x >> 5;
    int wm = warp & 1, wn = warp >> 1;
    int g = lane >> 2, tg = lane & 3;
    __half* C = g_exph + (size_t)b*SS*SS;
    float rs[4][2] = {};
    #pragma unroll
    for (int mi = 0; mi < 4; mi++){
        int r = m0 + wm*64 + mi*16 + g;
        #pragma unroll
        for (int ni = 0; ni < 8; ni++){
            int c = n0 + wn*64 + ni*8 + 2*tg;
            float e0 = __expf(acc[mi][ni][0]*scale);
            float e1 = __expf(acc[mi][ni][1]*scale);
            float e2 = __expf(acc[mi][ni][2]*scale);
            float e3 = __expf(acc[mi][ni][3]*scale);
            *(__half2*)(C + (size_t)r*SS + c)     = __floats2half2_rn(e0, e1);
            *(__half2*)(C + (size_t)(r+8)*SS + c) = __floats2half2_rn(e2, e3);
            rs[mi][0] += e0 + e1;
            rs[mi][1] += e2 + e3;
        }
    }
    #pragma unroll
    for (int mi = 0; mi < 4; mi++){
        #pragma unroll
        for (int h = 0; h < 2; h++){
            float v = rs[mi][h];
            v += __shfl_xor_sync(0xffffffffu, v, 1);
            v += __shfl_xor_sync(0xffffffffu, v, 2);
            if (tg == 0)
                atomicAdd(&g_rowsum[b*SS + m0 + wm*64 + mi*16 + g + h*8], v);
        }
    }
}

__global__ __launch_bounds__(256, 1) void pv_tc(float* out){
    extern __shared__ unsigned sh[];
    int b = blockIdx.z;
    int m0 = blockIdx.y*128, n0 = blockIdx.x*256;
    float acc[4][8][4] = {};
    gemm_main(sh, g_exph + (size_t)(b*SS + m0)*SS, SS,
                  g_vpt  + (size_t)(b*DD + n0)*SS, SS, SS/BKH, acc);

    int lane = threadIdx.x & 31, warp = threadIdx.x >> 5;
    int wm = warp & 1, wn = warp >> 1;
    int g = lane >> 2, tg = lane & 3;
    #pragma unroll
    for (int mi = 0; mi < 4; mi++){
        int r = m0 + wm*64 + mi*16 + g;
        float inv0 = 1.0f / g_rowsum[b*SS + r];
        float inv1 = 1.0f / g_rowsum[b*SS + r + 8];
        #pragma unroll
        for (int ni = 0; ni < 8; ni++){
            int c = n0 + wn*64 + ni*8 + 2*tg;
            *(float2*)(out + (size_t)(b*SS + r)*DD + c) =
                make_float2(acc[mi][ni][0]*inv0, acc[mi][ni][1]*inv0);
            *(float2*)(out + (size_t)(b*SS + r + 8)*DD + c) =
                make_float2(acc[mi][ni][2]*inv1, acc[mi][ni][3]*inv1);
        }
    }
}

// ================= launch =================
extern "C" void kernel_launch(void* const* d_in, const int* in_sizes, int n_in,
                              void* d_out, int out_size)
{
    const float* q  = (const float*)d_in[0];
    const float* k  = (const float*)d_in[1];
    const float* v  = (const float*)d_in[2];
    const float* Wq = (const float*)d_in[3];
    const float* bq = (const float*)d_in[4];
    const float* Wk = (const float*)d_in[5];
    const float* bk = (const float*)d_in[6];
    const float* Wv = (const float*)d_in[7];
    const float* bv = (const float*)d_in[8];
    float* out = (float*)d_out;

    cudaFuncSetAttribute(proj_tc,   cudaFuncAttributeMaxDynamicSharedMemorySize, SMEM_BYTES);
    cudaFuncSetAttribute(scores_tc, cudaFuncAttributeMaxDynamicSharedMemorySize, SMEM_BYTES);
    cudaFuncSetAttribute(pv_tc,     cudaFuncAttributeMaxDynamicSharedMemorySize, SMEM_BYTES);

    void* p_rowsum;
    cudaGetSymbolAddress(&p_rowsum, g_rowsum);

    cvt_half<<<dim3(4096, 1, 3), 256>>>((const float4*)q, (const float4*)k, (const float4*)v);
    wt_t<<<dim3(16, 16, 3), dim3(32, 8)>>>(Wq, Wk, Wv);
    cudaMemsetAsync(p_rowsum, 0, MTOT*sizeof(float));

    proj_tc  <<<dim3(2, 128, 3), 256, SMEM_BYTES>>>(bq, bk, bv);
    scores_tc<<<dim3(8, 16, 8),  256, SMEM_BYTES>>>();
    pv_tc    <<<dim3(2, 16, 8),  256, SMEM_BYTES>>>(out);
}